// round 2
// baseline (speedup 1.0000x reference)
#include <cuda_runtime.h>
#include <float.h>

// Problem constants (fixed by reference setup_inputs)
#define N 4096
#define D 512
#define MARGIN 200.0f

// GEMM tiling
#define BM 128
#define BN 128
#define BK 8
#define NSPLIT 8
#define JRANGE (N / NSPLIT)   // 512 columns per split
#define JTILES (JRANGE / BN)  // 4
#define KTILES (D / BK)       // 64

// Scratch (no allocations allowed -> __device__ globals)
__device__ float g_sq[N];
__device__ int   g_lbl[N];
__device__ float g_pos[NSPLIT * N];
__device__ float g_neg[NSPLIT * N];

// ---------------------------------------------------------------------------
// Kernel 1: row squared norms + label copy (one warp per row)
// NOTE: targets arrive as int32 (JAX default config downcasts int64 -> int32).
// ---------------------------------------------------------------------------
__global__ void prep_kernel(const float* __restrict__ X,
                            const int* __restrict__ tgt) {
    int warp = (blockIdx.x * blockDim.x + threadIdx.x) >> 5;
    int lane = threadIdx.x & 31;
    if (warp >= N) return;
    const float* row = X + (size_t)warp * D;
    float s = 0.f;
    #pragma unroll
    for (int k = lane; k < D; k += 32) { float v = row[k]; s += v * v; }
    #pragma unroll
    for (int off = 16; off; off >>= 1) s += __shfl_down_sync(0xffffffffu, s, off);
    if (lane == 0) {
        g_sq[warp]  = s;
        g_lbl[warp] = tgt[warp];
    }
}

// ---------------------------------------------------------------------------
// Kernel 2: fused gram-GEMM + per-row hardest-pos max / hardest-neg min.
// Block = 128 rows (blockIdx.x) x one of NSPLIT column ranges (blockIdx.y).
// 256 threads, 8x8 micro-tile per thread. Distance matrix never hits memory.
// ---------------------------------------------------------------------------
__global__ __launch_bounds__(256)
void dist_minmax_kernel(const float* __restrict__ X) {
    __shared__ __align__(16) float As[BK][BM + 4];  // +4 pad: keeps rows 16B-aligned, breaks conflicts
    __shared__ __align__(16) float Bs[BK][BN + 4];

    const int tid = threadIdx.x;
    const int tx  = tid & 15;        // column group (8 cols)
    const int ty  = tid >> 4;        // row group (8 rows)
    const int i0  = blockIdx.x * BM;
    const int split = blockIdx.y;

    float bestp[8], bestn[8];
    #pragma unroll
    for (int r = 0; r < 8; r++) { bestp[r] = -FLT_MAX; bestn[r] = FLT_MAX; }

    // Tile-load mapping: each thread brings one float4 of A and one of B per k-tile
    const int lrow  = tid >> 1;        // 0..127
    const int lcol4 = (tid & 1) * 4;   // 0 or 4

    for (int jt = 0; jt < JTILES; jt++) {
        const int j0 = split * JRANGE + jt * BN;

        float acc[8][8];
        #pragma unroll
        for (int r = 0; r < 8; r++)
            #pragma unroll
            for (int c = 0; c < 8; c++) acc[r][c] = 0.f;

        for (int kt = 0; kt < KTILES; kt++) {
            const int k0 = kt * BK;
            float4 av = *(const float4*)(X + (size_t)(i0 + lrow) * D + k0 + lcol4);
            float4 bv = *(const float4*)(X + (size_t)(j0 + lrow) * D + k0 + lcol4);
            As[lcol4 + 0][lrow] = av.x; As[lcol4 + 1][lrow] = av.y;
            As[lcol4 + 2][lrow] = av.z; As[lcol4 + 3][lrow] = av.w;
            Bs[lcol4 + 0][lrow] = bv.x; Bs[lcol4 + 1][lrow] = bv.y;
            Bs[lcol4 + 2][lrow] = bv.z; Bs[lcol4 + 3][lrow] = bv.w;
            __syncthreads();

            #pragma unroll
            for (int k = 0; k < BK; k++) {
                float a[8], b[8];
                *(float4*)(a)     = *(const float4*)(&As[k][ty * 8]);
                *(float4*)(a + 4) = *(const float4*)(&As[k][ty * 8 + 4]);
                *(float4*)(b)     = *(const float4*)(&Bs[k][tx * 8]);
                *(float4*)(b + 4) = *(const float4*)(&Bs[k][tx * 8 + 4]);
                #pragma unroll
                for (int r = 0; r < 8; r++)
                    #pragma unroll
                    for (int c = 0; c < 8; c++)
                        acc[r][c] = fmaf(a[r], b[c], acc[r][c]);
            }
            __syncthreads();
        }

        // Epilogue for this 128x128 tile: form distances, fold into running best
        #pragma unroll
        for (int c = 0; c < 8; c++) {
            const int j   = j0 + tx * 8 + c;
            const float jsq = g_sq[j];
            const int   jl  = g_lbl[j];
            #pragma unroll
            for (int r = 0; r < 8; r++) {
                const int i = i0 + ty * 8 + r;
                const float dist = g_sq[i] + jsq - 2.0f * acc[r][c];
                if (g_lbl[i] == jl) bestp[r] = fmaxf(bestp[r], dist);
                else                bestn[r] = fminf(bestn[r], dist);
            }
        }
    }

    // Reduce across the 16 tx threads that share each row group (width-16 shuffles)
    #pragma unroll
    for (int r = 0; r < 8; r++) {
        float p = bestp[r], n = bestn[r];
        #pragma unroll
        for (int off = 8; off; off >>= 1) {
            p = fmaxf(p, __shfl_down_sync(0xffffffffu, p, off, 16));
            n = fminf(n, __shfl_down_sync(0xffffffffu, n, off, 16));
        }
        if (tx == 0) {
            const int i = i0 + ty * 8 + r;
            g_pos[split * N + i] = p;
            g_neg[split * N + i] = n;
        }
    }
}

// ---------------------------------------------------------------------------
// Kernel 3: merge the NSPLIT partials, compute mean(relu(ap - an + margin))
// ---------------------------------------------------------------------------
__global__ void finalize_kernel(float* __restrict__ out) {
    __shared__ float red[256];
    const int tid = threadIdx.x;
    float s = 0.f;
    for (int i = tid; i < N; i += 256) {
        float p = -FLT_MAX, n = FLT_MAX;
        #pragma unroll
        for (int sp = 0; sp < NSPLIT; sp++) {
            p = fmaxf(p, g_pos[sp * N + i]);
            n = fminf(n, g_neg[sp * N + i]);
        }
        const float t = p - n + MARGIN;
        s += (t > 0.f) ? t : 0.f;
    }
    red[tid] = s;
    __syncthreads();
    #pragma unroll
    for (int off = 128; off; off >>= 1) {
        if (tid < off) red[tid] += red[tid + off];
        __syncthreads();
    }
    if (tid == 0) out[0] = red[0] / (float)N;
}

// ---------------------------------------------------------------------------
extern "C" void kernel_launch(void* const* d_in, const int* in_sizes, int n_in,
                              void* d_out, int out_size) {
    const float* X   = (const float*)d_in[0];
    const int*   tgt = (const int*)d_in[1];
    float*       out = (float*)d_out;

    prep_kernel<<<N / 8, 256>>>(X, tgt);                       // 512 blocks, 1 warp/row
    dist_minmax_kernel<<<dim3(N / BM, NSPLIT), 256>>>(X);      // 32 x 8 = 256 blocks
    finalize_kernel<<<1, 256>>>(out);
}

// round 4
// speedup vs baseline: 2.9522x; 2.9522x over previous
#include <cuda_runtime.h>
#include <cstdint>
#include <float.h>

// ---------------------------------------------------------------------------
// Problem constants
// ---------------------------------------------------------------------------
#define N 4096
#define D 512
#define MARGIN 200.0f

// Tiling
#define BM 128
#define BN 128
#define KC 32                 // k per smem stage
#define KT (D / KC)           // 16 k-tiles
#define PADK 36               // floats per smem row (32 + 4 pad)
#define NJT (N / BN)          // 32 j-tiles -> partial arrays

#define STG_BYTES (128 * PADK * 4)          // 18432 per matrix per stage
#define OFF_A(s)  ((s) * STG_BYTES)
#define OFF_B(s)  (2 * STG_BYTES + (s) * STG_BYTES)
#define OFF_REDP  (4 * STG_BYTES)           // 73728: [128][4] floats
#define OFF_REDN  (OFF_REDP + 2048)
#define OFF_JSQ   (OFF_REDN + 2048)         // 128 floats
#define OFF_JLBL  (OFF_JSQ + 512)           // 128 ints
#define SMEM_TOTAL (OFF_JLBL + 512)         // 78848 bytes

// ---------------------------------------------------------------------------
// Device scratch
// ---------------------------------------------------------------------------
__device__ float g_sq[N];
__device__ int   g_lbl[N];
__device__ float g_pos[NJT * N];
__device__ float g_neg[NJT * N];

// ---------------------------------------------------------------------------
// PTX helpers (sm_80+ features only — compiles for plain sm_100)
// ---------------------------------------------------------------------------
__device__ __forceinline__ uint32_t smem_u32(const void* p) {
    uint32_t a;
    asm("{ .reg .u64 t; cvta.to.shared.u64 t, %1; cvt.u32.u64 %0, t; }" : "=r"(a) : "l"(p));
    return a;
}
#define CP_ASYNC16(dst, src) \
    asm volatile("cp.async.cg.shared.global [%0], [%1], 16;" :: "r"(dst), "l"(src))
#define CP_COMMIT() asm volatile("cp.async.commit_group;" ::: "memory")
#define CP_WAIT0()  asm volatile("cp.async.wait_group 0;" ::: "memory")

__device__ __forceinline__ void mma_tf32(float c[4],
                                         uint32_t a0, uint32_t a1, uint32_t a2, uint32_t a3,
                                         uint32_t b0, uint32_t b1) {
    asm volatile(
        "mma.sync.aligned.m16n8k8.row.col.f32.tf32.tf32.f32 "
        "{%0,%1,%2,%3}, {%4,%5,%6,%7}, {%8,%9}, {%0,%1,%2,%3};"
        : "+f"(c[0]), "+f"(c[1]), "+f"(c[2]), "+f"(c[3])
        : "r"(a0), "r"(a1), "r"(a2), "r"(a3), "r"(b0), "r"(b1));
}

// ---------------------------------------------------------------------------
// Kernel 1: row squared norms + labels
// ---------------------------------------------------------------------------
__global__ void prep_kernel(const float* __restrict__ X, const int* __restrict__ tgt) {
    int warp = (blockIdx.x * blockDim.x + threadIdx.x) >> 5;
    int lane = threadIdx.x & 31;
    if (warp >= N) return;
    const float* row = X + (size_t)warp * D;
    float s = 0.f;
    #pragma unroll
    for (int k = lane; k < D; k += 32) { float v = row[k]; s += v * v; }
    #pragma unroll
    for (int off = 16; off; off >>= 1) s += __shfl_down_sync(0xffffffffu, s, off);
    if (lane == 0) { g_sq[warp] = s; g_lbl[warp] = tgt[warp]; }
}

// ---------------------------------------------------------------------------
// Kernel 2: tf32 mma.sync gram-GEMM (128x128 tile) fused with hardest-pos/neg.
// 8 warps in 2(m) x 4(n); each warp 64x32 via 4x4 m16n8k8 tiles.
// ---------------------------------------------------------------------------
__global__ __launch_bounds__(256)
void gemm_minmax_kernel(const float* __restrict__ X) {
    extern __shared__ char smem[];
    const uint32_t sbase = smem_u32(smem);
    const int tid  = threadIdx.x;
    const int warp = tid >> 5, lane = tid & 31;
    const int wm = warp & 1, wn = warp >> 1;     // 2 x 4 warp grid
    const int g = lane >> 2, t = lane & 3;
    const int i0 = blockIdx.x * BM;
    const int j0 = blockIdx.y * BN;
    const int jt = blockIdx.y;

    float* s_jsq  = (float*)(smem + OFF_JSQ);
    int*   s_jlbl = (int*)(smem + OFF_JLBL);
    if (tid < 128) { s_jsq[tid] = g_sq[j0 + tid]; s_jlbl[tid] = g_lbl[j0 + tid]; }

    float c[4][4][4];
    #pragma unroll
    for (int mt = 0; mt < 4; mt++)
        #pragma unroll
        for (int nt = 0; nt < 4; nt++)
            #pragma unroll
            for (int q = 0; q < 4; q++) c[mt][nt][q] = 0.f;

    // ---- cp.async tile loader: 1024 float4 per matrix, 4 per thread ----
    auto load_tile = [&](int kt, int s) {
        const int k0 = kt * KC;
        #pragma unroll
        for (int it = 0; it < 4; it++) {
            const int idx = it * 256 + tid;       // 0..1023
            const int row = idx >> 3;
            const int c4  = idx & 7;
            const uint32_t soff = (uint32_t)(row * PADK + c4 * 4) * 4u;
            CP_ASYNC16(sbase + OFF_A(s) + soff, X + (size_t)(i0 + row) * D + k0 + c4 * 4);
            CP_ASYNC16(sbase + OFF_B(s) + soff, X + (size_t)(j0 + row) * D + k0 + c4 * 4);
        }
        CP_COMMIT();
    };

    load_tile(0, 0);

    const char* pA_warp[2] = { smem + OFF_A(0) + (size_t)(wm * 64) * PADK * 4,
                               smem + OFF_A(1) + (size_t)(wm * 64) * PADK * 4 };
    const char* pB_warp[2] = { smem + OFF_B(0) + (size_t)(wn * 32) * PADK * 4,
                               smem + OFF_B(1) + (size_t)(wn * 32) * PADK * 4 };

    for (int kt = 0; kt < KT; kt++) {
        CP_WAIT0();
        __syncthreads();
        if (kt + 1 < KT) load_tile(kt + 1, (kt + 1) & 1);

        const float* A = (const float*)pA_warp[kt & 1];
        const float* B = (const float*)pB_warp[kt & 1];

        #pragma unroll
        for (int kk = 0; kk < 4; kk++) {
            const int ko = kk * 8;
            uint32_t a[4][4], b[4][2];
            #pragma unroll
            for (int mt = 0; mt < 4; mt++) {
                const float* r = A + (mt * 16 + g) * PADK + ko + t;
                a[mt][0] = __float_as_uint(r[0]);
                a[mt][1] = __float_as_uint(r[8 * PADK]);
                a[mt][2] = __float_as_uint(r[4]);
                a[mt][3] = __float_as_uint(r[8 * PADK + 4]);
            }
            #pragma unroll
            for (int nt = 0; nt < 4; nt++) {
                const float* r = B + (nt * 8 + g) * PADK + ko + t;
                b[nt][0] = __float_as_uint(r[0]);
                b[nt][1] = __float_as_uint(r[4]);
            }
            #pragma unroll
            for (int mt = 0; mt < 4; mt++)
                #pragma unroll
                for (int nt = 0; nt < 4; nt++)
                    mma_tf32(c[mt][nt], a[mt][0], a[mt][1], a[mt][2], a[mt][3],
                             b[nt][0], b[nt][1]);
        }
        __syncthreads();
    }

    // ---- epilogue: dist + fold into per-row bests ----
    float* red_p = (float*)(smem + OFF_REDP);   // [128][4]
    float* red_n = (float*)(smem + OFF_REDN);

    #pragma unroll
    for (int mt = 0; mt < 4; mt++) {
        const int rlo = wm * 64 + mt * 16 + g;      // local row in 0..127
        const int rhi = rlo + 8;
        const float isq_lo = g_sq[i0 + rlo], isq_hi = g_sq[i0 + rhi];
        const int   il_lo  = g_lbl[i0 + rlo], il_hi = g_lbl[i0 + rhi];
        float bpl = -FLT_MAX, bnl = FLT_MAX, bph = -FLT_MAX, bnh = FLT_MAX;
        #pragma unroll
        for (int nt = 0; nt < 4; nt++) {
            const int jc0 = wn * 32 + nt * 8 + 2 * t;
            const float jsq0 = s_jsq[jc0],  jsq1 = s_jsq[jc0 + 1];
            const int   jl0  = s_jlbl[jc0], jl1  = s_jlbl[jc0 + 1];
            float d;
            d = fmaf(-2.f, c[mt][nt][0], isq_lo + jsq0);
            if (il_lo == jl0) bpl = fmaxf(bpl, d); else bnl = fminf(bnl, d);
            d = fmaf(-2.f, c[mt][nt][1], isq_lo + jsq1);
            if (il_lo == jl1) bpl = fmaxf(bpl, d); else bnl = fminf(bnl, d);
            d = fmaf(-2.f, c[mt][nt][2], isq_hi + jsq0);
            if (il_hi == jl0) bph = fmaxf(bph, d); else bnh = fminf(bnh, d);
            d = fmaf(-2.f, c[mt][nt][3], isq_hi + jsq1);
            if (il_hi == jl1) bph = fmaxf(bph, d); else bnh = fminf(bnh, d);
        }
        // reduce across the 4 tg-lanes (same g)
        bpl = fmaxf(bpl, __shfl_down_sync(0xffffffffu, bpl, 2));
        bpl = fmaxf(bpl, __shfl_down_sync(0xffffffffu, bpl, 1));
        bnl = fminf(bnl, __shfl_down_sync(0xffffffffu, bnl, 2));
        bnl = fminf(bnl, __shfl_down_sync(0xffffffffu, bnl, 1));
        bph = fmaxf(bph, __shfl_down_sync(0xffffffffu, bph, 2));
        bph = fmaxf(bph, __shfl_down_sync(0xffffffffu, bph, 1));
        bnh = fminf(bnh, __shfl_down_sync(0xffffffffu, bnh, 2));
        bnh = fminf(bnh, __shfl_down_sync(0xffffffffu, bnh, 1));
        if (t == 0) {
            red_p[rlo * 4 + wn] = bpl; red_n[rlo * 4 + wn] = bnl;
            red_p[rhi * 4 + wn] = bph; red_n[rhi * 4 + wn] = bnh;
        }
    }
    __syncthreads();

    // fold across the 4 warp_n columns; one thread per row; contention-free store
    if (tid < 128) {
        float p = red_p[tid * 4 + 0], n = red_n[tid * 4 + 0];
        #pragma unroll
        for (int w = 1; w < 4; w++) {
            p = fmaxf(p, red_p[tid * 4 + w]);
            n = fminf(n, red_n[tid * 4 + w]);
        }
        g_pos[jt * N + i0 + tid] = p;
        g_neg[jt * N + i0 + tid] = n;
    }
}

// ---------------------------------------------------------------------------
// Kernel 3: fold partials, loss = mean(relu(ap - an + margin))
// ---------------------------------------------------------------------------
__global__ void finalize_kernel(float* __restrict__ out) {
    __shared__ float red[256];
    const int tid = threadIdx.x;
    float s = 0.f;
    for (int i = tid; i < N; i += 256) {
        float p = -FLT_MAX, n = FLT_MAX;
        #pragma unroll
        for (int sp = 0; sp < NJT; sp++) {
            p = fmaxf(p, g_pos[sp * N + i]);
            n = fminf(n, g_neg[sp * N + i]);
        }
        const float v = p - n + MARGIN;
        s += (v > 0.f) ? v : 0.f;
    }
    red[tid] = s;
    __syncthreads();
    #pragma unroll
    for (int off = 128; off; off >>= 1) {
        if (tid < off) red[tid] += red[tid + off];
        __syncthreads();
    }
    if (tid == 0) out[0] = red[0] / (float)N;
}

// ---------------------------------------------------------------------------
extern "C" void kernel_launch(void* const* d_in, const int* in_sizes, int n_in,
                              void* d_out, int out_size) {
    const float* X   = (const float*)d_in[0];
    const int*   tgt = (const int*)d_in[1];
    float*       out = (float*)d_out;

    cudaFuncSetAttribute(gemm_minmax_kernel,
                         cudaFuncAttributeMaxDynamicSharedMemorySize, SMEM_TOTAL);

    prep_kernel<<<N / 8, 256>>>(X, tgt);
    gemm_minmax_kernel<<<dim3(N / BM, N / BN), 256, SMEM_TOTAL>>>(X);
    finalize_kernel<<<1, 256>>>(out);
}

// round 5
// speedup vs baseline: 4.2734x; 1.4475x over previous
#include <cuda_runtime.h>
#include <cstdint>
#include <float.h>

// ---------------------------------------------------------------------------
// Problem constants
// ---------------------------------------------------------------------------
#define N 4096
#define D 512
#define MARGIN 200.0f

// Tiling
#define BM 128
#define BN 128
#define KC 32                 // k per smem stage
#define KT (D / KC)           // 16 k-tiles
#define PADK 36               // floats per smem row (32 + 4 pad)
#define NB (N / BM)           // 32 blocks per dim
#define NJT NB                // 32 partial slots per row

#define STG_BYTES (128 * PADK * 4)          // 18432 per matrix per stage
#define OFF_A(s)  ((s) * STG_BYTES)
#define OFF_B(s)  (2 * STG_BYTES + (s) * STG_BYTES)
#define OFF_REDP  (4 * STG_BYTES)           // 73728: [128][4] floats (row-fold across wn)
#define OFF_REDN  (OFF_REDP + 2048)
#define OFF_CP    (OFF_REDN + 2048)         // [2][128] floats (col-fold across wm)
#define OFF_CN    (OFF_CP + 1024)
#define OFF_JSQ   (OFF_CN + 1024)           // 128 floats
#define OFF_JLBL  (OFF_JSQ + 512)           // 128 ints
#define SMEM_TOTAL (OFF_JLBL + 512)

// ---------------------------------------------------------------------------
// Device scratch
// ---------------------------------------------------------------------------
__device__ float g_sq[N];
__device__ int   g_lbl[N];
__device__ float g_pos[NJT * N];
__device__ float g_neg[NJT * N];

// ---------------------------------------------------------------------------
// PTX helpers (sm_80+ only — compiles for plain sm_100 target)
// ---------------------------------------------------------------------------
__device__ __forceinline__ uint32_t smem_u32(const void* p) {
    uint32_t a;
    asm("{ .reg .u64 t; cvta.to.shared.u64 t, %1; cvt.u32.u64 %0, t; }" : "=r"(a) : "l"(p));
    return a;
}
#define CP_ASYNC16(dst, src) \
    asm volatile("cp.async.cg.shared.global [%0], [%1], 16;" :: "r"(dst), "l"(src))
#define CP_COMMIT() asm volatile("cp.async.commit_group;" ::: "memory")
#define CP_WAIT0()  asm volatile("cp.async.wait_group 0;" ::: "memory")

__device__ __forceinline__ void mma_tf32(float c[4],
                                         uint32_t a0, uint32_t a1, uint32_t a2, uint32_t a3,
                                         uint32_t b0, uint32_t b1) {
    asm volatile(
        "mma.sync.aligned.m16n8k8.row.col.f32.tf32.tf32.f32 "
        "{%0,%1,%2,%3}, {%4,%5,%6,%7}, {%8,%9}, {%0,%1,%2,%3};"
        : "+f"(c[0]), "+f"(c[1]), "+f"(c[2]), "+f"(c[3])
        : "r"(a0), "r"(a1), "r"(a2), "r"(a3), "r"(b0), "r"(b1));
}

// ---------------------------------------------------------------------------
// Kernel 1: row squared norms + labels (float4 loads)
// ---------------------------------------------------------------------------
__global__ void prep_kernel(const float* __restrict__ X, const int* __restrict__ tgt) {
    int warp = (blockIdx.x * blockDim.x + threadIdx.x) >> 5;
    int lane = threadIdx.x & 31;
    if (warp >= N) return;
    const float4* row = (const float4*)(X + (size_t)warp * D);
    float s = 0.f;
    #pragma unroll
    for (int k = lane; k < D / 4; k += 32) {
        float4 v = row[k];
        s += v.x * v.x + v.y * v.y + v.z * v.z + v.w * v.w;
    }
    #pragma unroll
    for (int off = 16; off; off >>= 1) s += __shfl_down_sync(0xffffffffu, s, off);
    if (lane == 0) { g_sq[warp] = s; g_lbl[warp] = tgt[warp]; }
}

// ---------------------------------------------------------------------------
// Kernel 2: tf32 mma.sync gram-GEMM over the UPPER TRIANGLE of block-tiles.
// Tile (bi,bj), bi<=bj. Row-fold -> rows of block bi (slot bj).
// Col-fold (off-diag only, symmetry) -> rows of block bj (slot bi).
// 8 warps in 2(m) x 4(n); each warp 64x32 via 4x4 m16n8k8 tiles.
// ---------------------------------------------------------------------------
__global__ __launch_bounds__(256)
void gemm_minmax_kernel(const float* __restrict__ X) {
    extern __shared__ char smem[];
    const uint32_t sbase = smem_u32(smem);
    const int tid  = threadIdx.x;
    const int warp = tid >> 5, lane = tid & 31;
    const int wm = warp & 1, wn = warp >> 1;     // 2 x 4 warp grid
    const int g = lane >> 2, t = lane & 3;

    // decode linear block index -> (bi, bj) with bi <= bj
    int bi = 0, rem = blockIdx.x;
    while (rem >= NB - bi) { rem -= NB - bi; bi++; }
    const int bj = bi + rem;
    const bool diag = (bi == bj);
    const int i0 = bi * BM;
    const int j0 = bj * BN;

    float* s_jsq  = (float*)(smem + OFF_JSQ);
    int*   s_jlbl = (int*)(smem + OFF_JLBL);
    if (tid < 128) { s_jsq[tid] = g_sq[j0 + tid]; s_jlbl[tid] = g_lbl[j0 + tid]; }

    float c[4][4][4];
    #pragma unroll
    for (int mt = 0; mt < 4; mt++)
        #pragma unroll
        for (int nt = 0; nt < 4; nt++)
            #pragma unroll
            for (int q = 0; q < 4; q++) c[mt][nt][q] = 0.f;

    // ---- cp.async tile loader ----
    auto load_tile = [&](int kt, int s) {
        const int k0 = kt * KC;
        #pragma unroll
        for (int it = 0; it < 4; it++) {
            const int idx = it * 256 + tid;       // 0..1023
            const int row = idx >> 3;
            const int c4  = idx & 7;
            const uint32_t soff = (uint32_t)(row * PADK + c4 * 4) * 4u;
            CP_ASYNC16(sbase + OFF_A(s) + soff, X + (size_t)(i0 + row) * D + k0 + c4 * 4);
            if (!diag)
                CP_ASYNC16(sbase + OFF_B(s) + soff, X + (size_t)(j0 + row) * D + k0 + c4 * 4);
        }
        CP_COMMIT();
    };

    load_tile(0, 0);

    const char* pA_warp[2] = { smem + OFF_A(0) + (size_t)(wm * 64) * PADK * 4,
                               smem + OFF_A(1) + (size_t)(wm * 64) * PADK * 4 };
    const char* pB_warp[2] = { diag ? smem + OFF_A(0) + (size_t)(wn * 32) * PADK * 4
                                    : smem + OFF_B(0) + (size_t)(wn * 32) * PADK * 4,
                               diag ? smem + OFF_A(1) + (size_t)(wn * 32) * PADK * 4
                                    : smem + OFF_B(1) + (size_t)(wn * 32) * PADK * 4 };

    for (int kt = 0; kt < KT; kt++) {
        CP_WAIT0();
        __syncthreads();
        if (kt + 1 < KT) load_tile(kt + 1, (kt + 1) & 1);

        const float* A = (const float*)pA_warp[kt & 1];
        const float* B = (const float*)pB_warp[kt & 1];

        #pragma unroll
        for (int kk = 0; kk < 4; kk++) {
            const int ko = kk * 8;
            uint32_t a[4][4], b[4][2];
            #pragma unroll
            for (int mt = 0; mt < 4; mt++) {
                const float* r = A + (mt * 16 + g) * PADK + ko + t;
                a[mt][0] = __float_as_uint(r[0]);
                a[mt][1] = __float_as_uint(r[8 * PADK]);
                a[mt][2] = __float_as_uint(r[4]);
                a[mt][3] = __float_as_uint(r[8 * PADK + 4]);
            }
            #pragma unroll
            for (int nt = 0; nt < 4; nt++) {
                const float* r = B + (nt * 8 + g) * PADK + ko + t;
                b[nt][0] = __float_as_uint(r[0]);
                b[nt][1] = __float_as_uint(r[4]);
            }
            #pragma unroll
            for (int mt = 0; mt < 4; mt++)
                #pragma unroll
                for (int nt = 0; nt < 4; nt++)
                    mma_tf32(c[mt][nt], a[mt][0], a[mt][1], a[mt][2], a[mt][3],
                             b[nt][0], b[nt][1]);
        }
        __syncthreads();
    }

    // ---- epilogue: distances + row-fold + (off-diag) col-fold ----
    float* red_p = (float*)(smem + OFF_REDP);   // [128][4] across wn
    float* red_n = (float*)(smem + OFF_REDN);
    float* col_p = (float*)(smem + OFF_CP);     // [2][128] across wm
    float* col_n = (float*)(smem + OFF_CN);

    float cp[4][2], cn[4][2];                   // per-thread col bests (2 cols per nt)
    #pragma unroll
    for (int nt = 0; nt < 4; nt++) { cp[nt][0] = cp[nt][1] = -FLT_MAX;
                                     cn[nt][0] = cn[nt][1] =  FLT_MAX; }

    #pragma unroll
    for (int mt = 0; mt < 4; mt++) {
        const int rlo = wm * 64 + mt * 16 + g;      // local row in 0..127
        const int rhi = rlo + 8;
        const float isq_lo = g_sq[i0 + rlo], isq_hi = g_sq[i0 + rhi];
        const int   il_lo  = g_lbl[i0 + rlo], il_hi = g_lbl[i0 + rhi];
        float bpl = -FLT_MAX, bnl = FLT_MAX, bph = -FLT_MAX, bnh = FLT_MAX;
        #pragma unroll
        for (int nt = 0; nt < 4; nt++) {
            const int jc0 = wn * 32 + nt * 8 + 2 * t;
            const float jsq0 = s_jsq[jc0],  jsq1 = s_jsq[jc0 + 1];
            const int   jl0  = s_jlbl[jc0], jl1  = s_jlbl[jc0 + 1];
            float d;
            d = fmaf(-2.f, c[mt][nt][0], isq_lo + jsq0);
            if (il_lo == jl0) { bpl = fmaxf(bpl, d); cp[nt][0] = fmaxf(cp[nt][0], d); }
            else              { bnl = fminf(bnl, d); cn[nt][0] = fminf(cn[nt][0], d); }
            d = fmaf(-2.f, c[mt][nt][1], isq_lo + jsq1);
            if (il_lo == jl1) { bpl = fmaxf(bpl, d); cp[nt][1] = fmaxf(cp[nt][1], d); }
            else              { bnl = fminf(bnl, d); cn[nt][1] = fminf(cn[nt][1], d); }
            d = fmaf(-2.f, c[mt][nt][2], isq_hi + jsq0);
            if (il_hi == jl0) { bph = fmaxf(bph, d); cp[nt][0] = fmaxf(cp[nt][0], d); }
            else              { bnh = fminf(bnh, d); cn[nt][0] = fminf(cn[nt][0], d); }
            d = fmaf(-2.f, c[mt][nt][3], isq_hi + jsq1);
            if (il_hi == jl1) { bph = fmaxf(bph, d); cp[nt][1] = fmaxf(cp[nt][1], d); }
            else              { bnh = fminf(bnh, d); cn[nt][1] = fminf(cn[nt][1], d); }
        }
        // row reduce across the 4 t-lanes (same g)
        bpl = fmaxf(bpl, __shfl_down_sync(0xffffffffu, bpl, 2));
        bpl = fmaxf(bpl, __shfl_down_sync(0xffffffffu, bpl, 1));
        bnl = fminf(bnl, __shfl_down_sync(0xffffffffu, bnl, 2));
        bnl = fminf(bnl, __shfl_down_sync(0xffffffffu, bnl, 1));
        bph = fmaxf(bph, __shfl_down_sync(0xffffffffu, bph, 2));
        bph = fmaxf(bph, __shfl_down_sync(0xffffffffu, bph, 1));
        bnh = fminf(bnh, __shfl_down_sync(0xffffffffu, bnh, 2));
        bnh = fminf(bnh, __shfl_down_sync(0xffffffffu, bnh, 1));
        if (t == 0) {
            red_p[rlo * 4 + wn] = bpl; red_n[rlo * 4 + wn] = bnl;
            red_p[rhi * 4 + wn] = bph; red_n[rhi * 4 + wn] = bnh;
        }
    }

    // col reduce across the 8 g-groups (lanes with same t), off-diag only
    if (!diag) {
        #pragma unroll
        for (int nt = 0; nt < 4; nt++) {
            #pragma unroll
            for (int q = 0; q < 2; q++) {
                float p = cp[nt][q], n = cn[nt][q];
                #pragma unroll
                for (int off = 4; off <= 16; off <<= 1) {
                    p = fmaxf(p, __shfl_xor_sync(0xffffffffu, p, off));
                    n = fminf(n, __shfl_xor_sync(0xffffffffu, n, off));
                }
                if (lane < 4) {
                    const int col = wn * 32 + nt * 8 + 2 * t + q;
                    col_p[wm * 128 + col] = p;
                    col_n[wm * 128 + col] = n;
                }
            }
        }
    }
    __syncthreads();

    if (tid < 128) {
        // row result -> slot bj, rows of block bi
        float p = red_p[tid * 4 + 0], n = red_n[tid * 4 + 0];
        #pragma unroll
        for (int w = 1; w < 4; w++) {
            p = fmaxf(p, red_p[tid * 4 + w]);
            n = fminf(n, red_n[tid * 4 + w]);
        }
        g_pos[bj * N + i0 + tid] = p;
        g_neg[bj * N + i0 + tid] = n;

        if (!diag) {
            // col result -> slot bi, rows of block bj
            float pc = fmaxf(col_p[tid], col_p[128 + tid]);
            float nc = fminf(col_n[tid], col_n[128 + tid]);
            g_pos[bi * N + j0 + tid] = pc;
            g_neg[bi * N + j0 + tid] = nc;
        }
    }
}

// ---------------------------------------------------------------------------
// Kernel 3: fold partials, loss = mean(relu(ap - an + margin))
// ---------------------------------------------------------------------------
__global__ void finalize_kernel(float* __restrict__ out) {
    __shared__ float red[256];
    const int tid = threadIdx.x;
    float s = 0.f;
    for (int i = tid; i < N; i += 256) {
        float p = -FLT_MAX, n = FLT_MAX;
        #pragma unroll
        for (int sp = 0; sp < NJT; sp++) {
            p = fmaxf(p, g_pos[sp * N + i]);
            n = fminf(n, g_neg[sp * N + i]);
        }
        const float v = p - n + MARGIN;
        s += (v > 0.f) ? v : 0.f;
    }
    red[tid] = s;
    __syncthreads();
    #pragma unroll
    for (int off = 128; off; off >>= 1) {
        if (tid < off) red[tid] += red[tid + off];
        __syncthreads();
    }
    if (tid == 0) out[0] = red[0] / (float)N;
}

// ---------------------------------------------------------------------------
extern "C" void kernel_launch(void* const* d_in, const int* in_sizes, int n_in,
                              void* d_out, int out_size) {
    const float* X   = (const float*)d_in[0];
    const int*   tgt = (const int*)d_in[1];
    float*       out = (float*)d_out;

    cudaFuncSetAttribute(gemm_minmax_kernel,
                         cudaFuncAttributeMaxDynamicSharedMemorySize, SMEM_TOTAL);

    const int ntiles = NB * (NB + 1) / 2;   // 528 upper-triangle tiles
    prep_kernel<<<N / 8, 256>>>(X, tgt);
    gemm_minmax_kernel<<<ntiles, 256, SMEM_TOTAL>>>(X);
    finalize_kernel<<<1, 256>>>(out);
}

// round 8
// speedup vs baseline: 5.6754x; 1.3281x over previous
#include <cuda_runtime.h>
#include <cuda_fp16.h>
#include <cstdint>
#include <float.h>

// ---------------------------------------------------------------------------
// Problem constants
// ---------------------------------------------------------------------------
#define N 4096
#define D 512
#define MARGIN 200.0f

// Tiling
#define BM 128
#define BN 128
#define KC 32                 // k per smem stage
#define KT (D / KC)           // 16 k-tiles
#define PADH 40               // halfs per smem row (32 + 8 pad) -> conflict-free
#define NB (N / BM)           // 32 blocks per dim
#define NJT NB

#define STG_H (128 * PADH * 2)              // 10240 B per matrix per stage
#define OFF_A(s)  ((s) * STG_H)
#define OFF_B(s)  (2 * STG_H + (s) * STG_H)
#define OFF_REDP  (4 * STG_H)               // 40960: [128][4] floats
#define OFF_REDN  (OFF_REDP + 2048)
#define OFF_CP    (OFF_REDN + 2048)         // [2][128] floats
#define OFF_CN    (OFF_CP + 1024)
#define OFF_JSQ   (OFF_CN + 1024)
#define OFF_JLBL  (OFF_JSQ + 512)
#define SMEM_TOTAL (OFF_JLBL + 512)         // 48128 bytes -> 2 CTAs/SM

// ---------------------------------------------------------------------------
// Device scratch (static module storage; no runtime allocation)
// ---------------------------------------------------------------------------
__device__ __half g_Xh[N * D];   // fp16 copy of X (4 MB)
__device__ float  g_sq[N];
__device__ int    g_lbl[N];
__device__ float  g_pos[NJT * N];
__device__ float  g_neg[NJT * N];

// ---------------------------------------------------------------------------
// PTX helpers (sm_80+ only — compiles for plain sm_100 target)
// ---------------------------------------------------------------------------
__device__ __forceinline__ uint32_t smem_u32(const void* p) {
    uint32_t a;
    asm("{ .reg .u64 t; cvta.to.shared.u64 t, %1; cvt.u32.u64 %0, t; }" : "=r"(a) : "l"(p));
    return a;
}
#define CP_ASYNC16(dst, src) \
    asm volatile("cp.async.cg.shared.global [%0], [%1], 16;" :: "r"(dst), "l"(src))
#define CP_COMMIT() asm volatile("cp.async.commit_group;" ::: "memory")
#define CP_WAIT0()  asm volatile("cp.async.wait_group 0;" ::: "memory")

__device__ __forceinline__ void mma_f16(float c[4],
                                        uint32_t a0, uint32_t a1, uint32_t a2, uint32_t a3,
                                        uint32_t b0, uint32_t b1) {
    asm volatile(
        "mma.sync.aligned.m16n8k16.row.col.f32.f16.f16.f32 "
        "{%0,%1,%2,%3}, {%4,%5,%6,%7}, {%8,%9}, {%0,%1,%2,%3};"
        : "+f"(c[0]), "+f"(c[1]), "+f"(c[2]), "+f"(c[3])
        : "r"(a0), "r"(a1), "r"(a2), "r"(a3), "r"(b0), "r"(b1));
}

// ---------------------------------------------------------------------------
// Kernel 1: row norms + labels + fp32 -> fp16 conversion (one warp per row)
// ---------------------------------------------------------------------------
__global__ void prep_kernel(const float* __restrict__ X, const int* __restrict__ tgt) {
    int warp = (blockIdx.x * blockDim.x + threadIdx.x) >> 5;
    int lane = threadIdx.x & 31;
    if (warp >= N) return;
    const float4* row = (const float4*)(X + (size_t)warp * D);
    __half2* hrow = (__half2*)(g_Xh + (size_t)warp * D);
    float s = 0.f;
    #pragma unroll
    for (int k = lane; k < D / 4; k += 32) {
        float4 v = row[k];
        s += v.x * v.x + v.y * v.y + v.z * v.z + v.w * v.w;
        hrow[2 * k]     = __floats2half2_rn(v.x, v.y);
        hrow[2 * k + 1] = __floats2half2_rn(v.z, v.w);
    }
    #pragma unroll
    for (int off = 16; off; off >>= 1) s += __shfl_down_sync(0xffffffffu, s, off);
    if (lane == 0) { g_sq[warp] = s; g_lbl[warp] = tgt[warp]; }
}

// ---------------------------------------------------------------------------
// Kernel 2: fp16 mma.sync gram-GEMM over the UPPER TRIANGLE of block-tiles.
// Tile (bi,bj), bi<=bj. Row-fold -> rows of bi (slot bj); col-fold (off-diag,
// symmetry) -> rows of bj (slot bi). 8 warps 2(m) x 4(n); warp tile 64x32.
// ---------------------------------------------------------------------------
__global__ __launch_bounds__(256, 2)
void gemm_minmax_kernel() {
    extern __shared__ char smem[];
    const uint32_t sbase = smem_u32(smem);
    const int tid  = threadIdx.x;
    const int warp = tid >> 5, lane = tid & 31;
    const int wm = warp & 1, wn = warp >> 1;
    const int g = lane >> 2, t = lane & 3;

    // decode linear block index -> (bi, bj) with bi <= bj
    int bi = 0, rem = blockIdx.x;
    while (rem >= NB - bi) { rem -= NB - bi; bi++; }
    const int bj = bi + rem;
    const bool diag = (bi == bj);
    const int i0 = bi * BM;
    const int j0 = bj * BN;

    float* s_jsq  = (float*)(smem + OFF_JSQ);
    int*   s_jlbl = (int*)(smem + OFF_JLBL);
    if (tid < 128) { s_jsq[tid] = g_sq[j0 + tid]; s_jlbl[tid] = g_lbl[j0 + tid]; }

    float c[4][4][4];
    #pragma unroll
    for (int mt = 0; mt < 4; mt++)
        #pragma unroll
        for (int nt = 0; nt < 4; nt++)
            #pragma unroll
            for (int q = 0; q < 4; q++) c[mt][nt][q] = 0.f;

    // ---- cp.async loader: 512 x 16B chunks per matrix, 2 per thread ----
    auto load_tile = [&](int kt, int s) {
        const int k0 = kt * KC;
        #pragma unroll
        for (int it = 0; it < 2; it++) {
            const int idx = it * 256 + tid;       // 0..511
            const int row = idx >> 2;
            const int cc  = idx & 3;
            const uint32_t soff = (uint32_t)(row * (PADH * 2) + cc * 16);
            CP_ASYNC16(sbase + OFF_A(s) + soff, g_Xh + (size_t)(i0 + row) * D + k0 + cc * 8);
            if (!diag)
                CP_ASYNC16(sbase + OFF_B(s) + soff, g_Xh + (size_t)(j0 + row) * D + k0 + cc * 8);
        }
        CP_COMMIT();
    };

    load_tile(0, 0);

    const char* pA_warp[2] = { smem + OFF_A(0) + (size_t)(wm * 64) * PADH * 2,
                               smem + OFF_A(1) + (size_t)(wm * 64) * PADH * 2 };
    const char* pB_warp[2] = { diag ? smem + OFF_A(0) + (size_t)(wn * 32) * PADH * 2
                                    : smem + OFF_B(0) + (size_t)(wn * 32) * PADH * 2,
                               diag ? smem + OFF_A(1) + (size_t)(wn * 32) * PADH * 2
                                    : smem + OFF_B(1) + (size_t)(wn * 32) * PADH * 2 };

    for (int kt = 0; kt < KT; kt++) {
        CP_WAIT0();
        __syncthreads();
        if (kt + 1 < KT) load_tile(kt + 1, (kt + 1) & 1);

        const __half* A = (const __half*)pA_warp[kt & 1];
        const __half* B = (const __half*)pB_warp[kt & 1];

        #pragma unroll
        for (int kk = 0; kk < 2; kk++) {           // k = 16 per mma
            const int ko = kk * 16;
            uint32_t a[4][4], b[4][2];
            #pragma unroll
            for (int mt = 0; mt < 4; mt++) {
                const __half* r = A + (mt * 16 + g) * PADH + ko + 2 * t;
                a[mt][0] = *(const uint32_t*)(r);
                a[mt][1] = *(const uint32_t*)(r + 8 * PADH);
                a[mt][2] = *(const uint32_t*)(r + 8);
                a[mt][3] = *(const uint32_t*)(r + 8 * PADH + 8);
            }
            #pragma unroll
            for (int nt = 0; nt < 4; nt++) {
                const __half* r = B + (nt * 8 + g) * PADH + ko + 2 * t;
                b[nt][0] = *(const uint32_t*)(r);
                b[nt][1] = *(const uint32_t*)(r + 8);
            }
            #pragma unroll
            for (int mt = 0; mt < 4; mt++)
                #pragma unroll
                for (int nt = 0; nt < 4; nt++)
                    mma_f16(c[mt][nt], a[mt][0], a[mt][1], a[mt][2], a[mt][3],
                            b[nt][0], b[nt][1]);
        }
        __syncthreads();
    }

    // ---- epilogue: distances + row-fold + (off-diag) col-fold ----
    float* red_p = (float*)(smem + OFF_REDP);
    float* red_n = (float*)(smem + OFF_REDN);
    float* col_p = (float*)(smem + OFF_CP);
    float* col_n = (float*)(smem + OFF_CN);

    float cp[4][2], cn[4][2];
    #pragma unroll
    for (int nt = 0; nt < 4; nt++) { cp[nt][0] = cp[nt][1] = -FLT_MAX;
                                     cn[nt][0] = cn[nt][1] =  FLT_MAX; }

    #pragma unroll
    for (int mt = 0; mt < 4; mt++) {
        const int rlo = wm * 64 + mt * 16 + g;
        const int rhi = rlo + 8;
        const float isq_lo = g_sq[i0 + rlo], isq_hi = g_sq[i0 + rhi];
        const int   il_lo  = g_lbl[i0 + rlo], il_hi = g_lbl[i0 + rhi];
        float bpl = -FLT_MAX, bnl = FLT_MAX, bph = -FLT_MAX, bnh = FLT_MAX;
        #pragma unroll
        for (int nt = 0; nt < 4; nt++) {
            const int jc0 = wn * 32 + nt * 8 + 2 * t;
            const float jsq0 = s_jsq[jc0],  jsq1 = s_jsq[jc0 + 1];
            const int   jl0  = s_jlbl[jc0], jl1  = s_jlbl[jc0 + 1];
            float d;
            d = fmaf(-2.f, c[mt][nt][0], isq_lo + jsq0);
            if (il_lo == jl0) { bpl = fmaxf(bpl, d); cp[nt][0] = fmaxf(cp[nt][0], d); }
            else              { bnl = fminf(bnl, d); cn[nt][0] = fminf(cn[nt][0], d); }
            d = fmaf(-2.f, c[mt][nt][1], isq_lo + jsq1);
            if (il_lo == jl1) { bpl = fmaxf(bpl, d); cp[nt][1] = fmaxf(cp[nt][1], d); }
            else              { bnl = fminf(bnl, d); cn[nt][1] = fminf(cn[nt][1], d); }
            d = fmaf(-2.f, c[mt][nt][2], isq_hi + jsq0);
            if (il_hi == jl0) { bph = fmaxf(bph, d); cp[nt][0] = fmaxf(cp[nt][0], d); }
            else              { bnh = fminf(bnh, d); cn[nt][0] = fminf(cn[nt][0], d); }
            d = fmaf(-2.f, c[mt][nt][3], isq_hi + jsq1);
            if (il_hi == jl1) { bph = fmaxf(bph, d); cp[nt][1] = fmaxf(cp[nt][1], d); }
            else              { bnh = fminf(bnh, d); cn[nt][1] = fminf(cn[nt][1], d); }
        }
        bpl = fmaxf(bpl, __shfl_down_sync(0xffffffffu, bpl, 2));
        bpl = fmaxf(bpl, __shfl_down_sync(0xffffffffu, bpl, 1));
        bnl = fminf(bnl, __shfl_down_sync(0xffffffffu, bnl, 2));
        bnl = fminf(bnl, __shfl_down_sync(0xffffffffu, bnl, 1));
        bph = fmaxf(bph, __shfl_down_sync(0xffffffffu, bph, 2));
        bph = fmaxf(bph, __shfl_down_sync(0xffffffffu, bph, 1));
        bnh = fminf(bnh, __shfl_down_sync(0xffffffffu, bnh, 2));
        bnh = fminf(bnh, __shfl_down_sync(0xffffffffu, bnh, 1));
        if (t == 0) {
            red_p[rlo * 4 + wn] = bpl; red_n[rlo * 4 + wn] = bnl;
            red_p[rhi * 4 + wn] = bph; red_n[rhi * 4 + wn] = bnh;
        }
    }

    if (!diag) {
        #pragma unroll
        for (int nt = 0; nt < 4; nt++) {
            #pragma unroll
            for (int q = 0; q < 2; q++) {
                float p = cp[nt][q], n = cn[nt][q];
                #pragma unroll
                for (int off = 4; off <= 16; off <<= 1) {
                    p = fmaxf(p, __shfl_xor_sync(0xffffffffu, p, off));
                    n = fminf(n, __shfl_xor_sync(0xffffffffu, n, off));
                }
                if (lane < 4) {
                    const int col = wn * 32 + nt * 8 + 2 * t + q;
                    col_p[wm * 128 + col] = p;
                    col_n[wm * 128 + col] = n;
                }
            }
        }
    }
    __syncthreads();

    if (tid < 128) {
        float p = red_p[tid * 4 + 0], n = red_n[tid * 4 + 0];
        #pragma unroll
        for (int w = 1; w < 4; w++) {
            p = fmaxf(p, red_p[tid * 4 + w]);
            n = fminf(n, red_n[tid * 4 + w]);
        }
        g_pos[bj * N + i0 + tid] = p;
        g_neg[bj * N + i0 + tid] = n;

        if (!diag) {
            float pc = fmaxf(col_p[tid], col_p[128 + tid]);
            float nc = fminf(col_n[tid], col_n[128 + tid]);
            g_pos[bi * N + j0 + tid] = pc;
            g_neg[bi * N + j0 + tid] = nc;
        }
    }
}

// ---------------------------------------------------------------------------
// Kernel 3: fold partials, loss = mean(relu(ap - an + margin))
// ---------------------------------------------------------------------------
__global__ void finalize_kernel(float* __restrict__ out) {
    __shared__ float red[256];
    const int tid = threadIdx.x;
    float s = 0.f;
    for (int i = tid; i < N; i += 256) {
        float p = -FLT_MAX, n = FLT_MAX;
        #pragma unroll
        for (int sp = 0; sp < NJT; sp++) {
            p = fmaxf(p, g_pos[sp * N + i]);
            n = fminf(n, g_neg[sp * N + i]);
        }
        const float v = p - n + MARGIN;
        s += (v > 0.f) ? v : 0.f;
    }
    red[tid] = s;
    __syncthreads();
    #pragma unroll
    for (int off = 128; off; off >>= 1) {
        if (tid < off) red[tid] += red[tid + off];
        __syncthreads();
    }
    if (tid == 0) out[0] = red[0] / (float)N;
}

// ---------------------------------------------------------------------------
extern "C" void kernel_launch(void* const* d_in, const int* in_sizes, int n_in,
                              void* d_out, int out_size) {
    const float* X   = (const float*)d_in[0];
    const int*   tgt = (const int*)d_in[1];
    float*       out = (float*)d_out;

    const int ntiles = NB * (NB + 1) / 2;   // 528 upper-triangle tiles
    prep_kernel<<<N / 8, 256>>>(X, tgt);
    gemm_minmax_kernel<<<ntiles, 256, SMEM_TOTAL>>>();
    finalize_kernel<<<1, 256>>>(out);
}

// round 9
// speedup vs baseline: 7.1540x; 1.2605x over previous
#include <cuda_runtime.h>
#include <cuda_fp16.h>
#include <cstdint>
#include <float.h>

// ---------------------------------------------------------------------------
// Problem constants
// ---------------------------------------------------------------------------
#define N 4096
#define D 512
#define MARGIN 200.0f

// Tiling
#define BM 128
#define BN 128
#define KC 32                 // k per smem stage
#define KT (D / KC)           // 16 k-tiles
#define PADH 40               // halfs per smem row (32 + 8 pad) -> ldmatrix conflict-free
#define NB (N / BM)           // 32 blocks per dim
#define NJT NB

#define STG_H (128 * PADH * 2)              // 10240 B per matrix per stage
#define OFF_A(s)  ((s) * STG_H)
#define OFF_B(s)  (2 * STG_H + (s) * STG_H)
#define OFF_REDP  (4 * STG_H)               // 40960: [128][4] floats
#define OFF_REDN  (OFF_REDP + 2048)
#define OFF_CP    (OFF_REDN + 2048)         // [2][128] floats
#define OFF_CN    (OFF_CP + 1024)
#define OFF_JSQ   (OFF_CN + 1024)
#define OFF_JLBL  (OFF_JSQ + 512)
#define SMEM_TOTAL (OFF_JLBL + 512)         // 48128 bytes -> 2 CTAs/SM

// ---------------------------------------------------------------------------
// Device scratch (static module storage; no runtime allocation)
// ---------------------------------------------------------------------------
__device__ __half g_Xh[N * D];   // fp16 copy of X (4 MB)
__device__ float  g_sq[N];
__device__ int    g_lbl[N];
__device__ float  g_pos[NJT * N];
__device__ float  g_neg[NJT * N];

// ---------------------------------------------------------------------------
// PTX helpers (sm_80 features only — compiles for plain sm_100 target)
// ---------------------------------------------------------------------------
__device__ __forceinline__ uint32_t smem_u32(const void* p) {
    uint32_t a;
    asm("{ .reg .u64 t; cvta.to.shared.u64 t, %1; cvt.u32.u64 %0, t; }" : "=r"(a) : "l"(p));
    return a;
}
#define CP_ASYNC16(dst, src) \
    asm volatile("cp.async.cg.shared.global [%0], [%1], 16;" :: "r"(dst), "l"(src))
#define CP_COMMIT() asm volatile("cp.async.commit_group;" ::: "memory")
#define CP_WAIT0()  asm volatile("cp.async.wait_group 0;" ::: "memory")

#define LDMATRIX_X4(r0, r1, r2, r3, addr) \
    asm volatile("ldmatrix.sync.aligned.m8n8.x4.shared.b16 {%0,%1,%2,%3}, [%4];" \
                 : "=r"(r0), "=r"(r1), "=r"(r2), "=r"(r3) : "r"(addr))

__device__ __forceinline__ void mma_f16(float c[4],
                                        uint32_t a0, uint32_t a1, uint32_t a2, uint32_t a3,
                                        uint32_t b0, uint32_t b1) {
    asm volatile(
        "mma.sync.aligned.m16n8k16.row.col.f32.f16.f16.f32 "
        "{%0,%1,%2,%3}, {%4,%5,%6,%7}, {%8,%9}, {%0,%1,%2,%3};"
        : "+f"(c[0]), "+f"(c[1]), "+f"(c[2]), "+f"(c[3])
        : "r"(a0), "r"(a1), "r"(a2), "r"(a3), "r"(b0), "r"(b1));
}

// ---------------------------------------------------------------------------
// Kernel 1: row norms + labels + fp32 -> fp16 conversion (one warp per row)
// ---------------------------------------------------------------------------
__global__ void prep_kernel(const float* __restrict__ X, const int* __restrict__ tgt) {
    int warp = (blockIdx.x * blockDim.x + threadIdx.x) >> 5;
    int lane = threadIdx.x & 31;
    if (warp >= N) return;
    const float4* row = (const float4*)(X + (size_t)warp * D);
    __half2* hrow = (__half2*)(g_Xh + (size_t)warp * D);
    float s = 0.f;
    #pragma unroll
    for (int k = lane; k < D / 4; k += 32) {
        float4 v = row[k];
        s += v.x * v.x + v.y * v.y + v.z * v.z + v.w * v.w;
        hrow[2 * k]     = __floats2half2_rn(v.x, v.y);
        hrow[2 * k + 1] = __floats2half2_rn(v.z, v.w);
    }
    #pragma unroll
    for (int off = 16; off; off >>= 1) s += __shfl_down_sync(0xffffffffu, s, off);
    if (lane == 0) { g_sq[warp] = s; g_lbl[warp] = tgt[warp]; }
}

// ---------------------------------------------------------------------------
// Kernel 2: fp16 mma.sync gram-GEMM over the UPPER TRIANGLE of block-tiles.
// Fragment loads via ldmatrix.x4 (6 shared-loads per 32 MMAs instead of 24).
// Tile (bi,bj), bi<=bj. Row-fold -> rows of bi (slot bj); col-fold (off-diag,
// symmetry) -> rows of bj (slot bi). 8 warps 2(m) x 4(n); warp tile 64x32.
// ---------------------------------------------------------------------------
__global__ __launch_bounds__(256, 2)
void gemm_minmax_kernel() {
    extern __shared__ char smem[];
    const uint32_t sbase = smem_u32(smem);
    const int tid  = threadIdx.x;
    const int warp = tid >> 5, lane = tid & 31;
    const int wm = warp & 1, wn = warp >> 1;
    const int g = lane >> 2, t = lane & 3;

    // decode linear block index -> (bi, bj) with bi <= bj
    int bi = 0, rem = blockIdx.x;
    while (rem >= NB - bi) { rem -= NB - bi; bi++; }
    const int bj = bi + rem;
    const bool diag = (bi == bj);
    const int i0 = bi * BM;
    const int j0 = bj * BN;

    float* s_jsq  = (float*)(smem + OFF_JSQ);
    int*   s_jlbl = (int*)(smem + OFF_JLBL);
    if (tid < 128) { s_jsq[tid] = g_sq[j0 + tid]; s_jlbl[tid] = g_lbl[j0 + tid]; }

    float c[4][4][4];
    #pragma unroll
    for (int mt = 0; mt < 4; mt++)
        #pragma unroll
        for (int nt = 0; nt < 4; nt++)
            #pragma unroll
            for (int q = 0; q < 4; q++) c[mt][nt][q] = 0.f;

    // ---- cp.async loader: 512 x 16B chunks per matrix, 2 per thread ----
    auto load_tile = [&](int kt, int s) {
        const int k0 = kt * KC;
        #pragma unroll
        for (int it = 0; it < 2; it++) {
            const int idx = it * 256 + tid;       // 0..511
            const int row = idx >> 2;
            const int cc  = idx & 3;
            const uint32_t soff = (uint32_t)(row * (PADH * 2) + cc * 16);
            CP_ASYNC16(sbase + OFF_A(s) + soff, g_Xh + (size_t)(i0 + row) * D + k0 + cc * 8);
            if (!diag)
                CP_ASYNC16(sbase + OFF_B(s) + soff, g_Xh + (size_t)(j0 + row) * D + k0 + cc * 8);
        }
        CP_COMMIT();
    };

    load_tile(0, 0);

    // ---- per-lane ldmatrix offsets (bytes within a tile) ----
    // A (m16k16, x4: m0=rows0-7 klo, m1=rows8-15 klo, m2=rows0-7 khi, m3=rows8-15 khi):
    //   lanes 0-15 -> row = lane, k+0 ; lanes 16-31 -> row = lane-16, k+8
    const uint32_t offA = (uint32_t)(((lane & 15) * PADH + (lane >> 4) * 8) * 2);
    // B (two n8k16 tiles, x4: m0=nt-even klo, m1=nt-even khi, m2=nt-odd klo, m3=nt-odd khi):
    //   row = (lane&7) + ((lane>>4)&1)*8 ; k += ((lane>>3)&1)*8
    const uint32_t offB = (uint32_t)((((lane & 7) + ((lane >> 4) & 1) * 8) * PADH
                                     + ((lane >> 3) & 1) * 8) * 2);

    const uint32_t aw = (uint32_t)(wm * 64) * PADH * 2u;   // warp row offset in A
    const uint32_t bw = (uint32_t)(wn * 32) * PADH * 2u;   // warp row offset in B

    const uint32_t baseA[2] = { sbase + OFF_A(0) + aw + offA, sbase + OFF_A(1) + aw + offA };
    const uint32_t baseB[2] = { diag ? sbase + OFF_A(0) + bw + offB : sbase + OFF_B(0) + bw + offB,
                                diag ? sbase + OFF_A(1) + bw + offB : sbase + OFF_B(1) + bw + offB };

    for (int kt = 0; kt < KT; kt++) {
        CP_WAIT0();
        __syncthreads();
        if (kt + 1 < KT) load_tile(kt + 1, (kt + 1) & 1);

        const uint32_t bA = baseA[kt & 1];
        const uint32_t bB = baseB[kt & 1];

        #pragma unroll
        for (int kk = 0; kk < 2; kk++) {           // k = 16 per mma
            const uint32_t ko = kk * 32;           // 16 halfs = 32 bytes
            uint32_t a[4][4], b[4][2];
            #pragma unroll
            for (int mt = 0; mt < 4; mt++)
                LDMATRIX_X4(a[mt][0], a[mt][1], a[mt][2], a[mt][3],
                            bA + (uint32_t)(mt * 16) * PADH * 2u + ko);
            #pragma unroll
            for (int p = 0; p < 2; p++)
                LDMATRIX_X4(b[2 * p][0], b[2 * p][1], b[2 * p + 1][0], b[2 * p + 1][1],
                            bB + (uint32_t)(p * 16) * PADH * 2u + ko);
            #pragma unroll
            for (int mt = 0; mt < 4; mt++)
                #pragma unroll
                for (int nt = 0; nt < 4; nt++)
                    mma_f16(c[mt][nt], a[mt][0], a[mt][1], a[mt][2], a[mt][3],
                            b[nt][0], b[nt][1]);
        }
        __syncthreads();
    }

    // ---- epilogue: distances + row-fold + (off-diag) col-fold ----
    float* red_p = (float*)(smem + OFF_REDP);
    float* red_n = (float*)(smem + OFF_REDN);
    float* col_p = (float*)(smem + OFF_CP);
    float* col_n = (float*)(smem + OFF_CN);

    float cp[4][2], cn[4][2];
    #pragma unroll
    for (int nt = 0; nt < 4; nt++) { cp[nt][0] = cp[nt][1] = -FLT_MAX;
                                     cn[nt][0] = cn[nt][1] =  FLT_MAX; }

    #pragma unroll
    for (int mt = 0; mt < 4; mt++) {
        const int rlo = wm * 64 + mt * 16 + g;
        const int rhi = rlo + 8;
        const float isq_lo = g_sq[i0 + rlo], isq_hi = g_sq[i0 + rhi];
        const int   il_lo  = g_lbl[i0 + rlo], il_hi = g_lbl[i0 + rhi];
        float bpl = -FLT_MAX, bnl = FLT_MAX, bph = -FLT_MAX, bnh = FLT_MAX;
        #pragma unroll
        for (int nt = 0; nt < 4; nt++) {
            const int jc0 = wn * 32 + nt * 8 + 2 * t;
            const float jsq0 = s_jsq[jc0],  jsq1 = s_jsq[jc0 + 1];
            const int   jl0  = s_jlbl[jc0], jl1  = s_jlbl[jc0 + 1];
            float d;
            d = fmaf(-2.f, c[mt][nt][0], isq_lo + jsq0);
            if (il_lo == jl0) { bpl = fmaxf(bpl, d); cp[nt][0] = fmaxf(cp[nt][0], d); }
            else              { bnl = fminf(bnl, d); cn[nt][0] = fminf(cn[nt][0], d); }
            d = fmaf(-2.f, c[mt][nt][1], isq_lo + jsq1);
            if (il_lo == jl1) { bpl = fmaxf(bpl, d); cp[nt][1] = fmaxf(cp[nt][1], d); }
            else              { bnl = fminf(bnl, d); cn[nt][1] = fminf(cn[nt][1], d); }
            d = fmaf(-2.f, c[mt][nt][2], isq_hi + jsq0);
            if (il_hi == jl0) { bph = fmaxf(bph, d); cp[nt][0] = fmaxf(cp[nt][0], d); }
            else              { bnh = fminf(bnh, d); cn[nt][0] = fminf(cn[nt][0], d); }
            d = fmaf(-2.f, c[mt][nt][3], isq_hi + jsq1);
            if (il_hi == jl1) { bph = fmaxf(bph, d); cp[nt][1] = fmaxf(cp[nt][1], d); }
            else              { bnh = fminf(bnh, d); cn[nt][1] = fminf(cn[nt][1], d); }
        }
        bpl = fmaxf(bpl, __shfl_down_sync(0xffffffffu, bpl, 2));
        bpl = fmaxf(bpl, __shfl_down_sync(0xffffffffu, bpl, 1));
        bnl = fminf(bnl, __shfl_down_sync(0xffffffffu, bnl, 2));
        bnl = fminf(bnl, __shfl_down_sync(0xffffffffu, bnl, 1));
        bph = fmaxf(bph, __shfl_down_sync(0xffffffffu, bph, 2));
        bph = fmaxf(bph, __shfl_down_sync(0xffffffffu, bph, 1));
        bnh = fminf(bnh, __shfl_down_sync(0xffffffffu, bnh, 2));
        bnh = fminf(bnh, __shfl_down_sync(0xffffffffu, bnh, 1));
        if (t == 0) {
            red_p[rlo * 4 + wn] = bpl; red_n[rlo * 4 + wn] = bnl;
            red_p[rhi * 4 + wn] = bph; red_n[rhi * 4 + wn] = bnh;
        }
    }

    if (!diag) {
        #pragma unroll
        for (int nt = 0; nt < 4; nt++) {
            #pragma unroll
            for (int q = 0; q < 2; q++) {
                float p = cp[nt][q], n = cn[nt][q];
                #pragma unroll
                for (int off = 4; off <= 16; off <<= 1) {
                    p = fmaxf(p, __shfl_xor_sync(0xffffffffu, p, off));
                    n = fminf(n, __shfl_xor_sync(0xffffffffu, n, off));
                }
                if (lane < 4) {
                    const int col = wn * 32 + nt * 8 + 2 * t + q;
                    col_p[wm * 128 + col] = p;
                    col_n[wm * 128 + col] = n;
                }
            }
        }
    }
    __syncthreads();

    if (tid < 128) {
        float p = red_p[tid * 4 + 0], n = red_n[tid * 4 + 0];
        #pragma unroll
        for (int w = 1; w < 4; w++) {
            p = fmaxf(p, red_p[tid * 4 + w]);
            n = fminf(n, red_n[tid * 4 + w]);
        }
        g_pos[bj * N + i0 + tid] = p;
        g_neg[bj * N + i0 + tid] = n;

        if (!diag) {
            float pc = fmaxf(col_p[tid], col_p[128 + tid]);
            float nc = fminf(col_n[tid], col_n[128 + tid]);
            g_pos[bi * N + j0 + tid] = pc;
            g_neg[bi * N + j0 + tid] = nc;
        }
    }
}

// ---------------------------------------------------------------------------
// Kernel 3: fold partials, loss = mean(relu(ap - an + margin))
// ---------------------------------------------------------------------------
__global__ void finalize_kernel(float* __restrict__ out) {
    __shared__ float red[256];
    const int tid = threadIdx.x;
    float s = 0.f;
    for (int i = tid; i < N; i += 256) {
        float p = -FLT_MAX, n = FLT_MAX;
        #pragma unroll
        for (int sp = 0; sp < NJT; sp++) {
            p = fmaxf(p, g_pos[sp * N + i]);
            n = fminf(n, g_neg[sp * N + i]);
        }
        const float v = p - n + MARGIN;
        s += (v > 0.f) ? v : 0.f;
    }
    red[tid] = s;
    __syncthreads();
    #pragma unroll
    for (int off = 128; off; off >>= 1) {
        if (tid < off) red[tid] += red[tid + off];
        __syncthreads();
    }
    if (tid == 0) out[0] = red[0] / (float)N;
}

// ---------------------------------------------------------------------------
extern "C" void kernel_launch(void* const* d_in, const int* in_sizes, int n_in,
                              void* d_out, int out_size) {
    const float* X   = (const float*)d_in[0];
    const int*   tgt = (const int*)d_in[1];
    float*       out = (float*)d_out;

    const int ntiles = NB * (NB + 1) / 2;   // 528 upper-triangle tiles
    prep_kernel<<<N / 8, 256>>>(X, tgt);
    gemm_minmax_kernel<<<ntiles, 256, SMEM_TOTAL>>>();
    finalize_kernel<<<1, 256>>>(out);
}